// round 4
// baseline (speedup 1.0000x reference)
#include <cuda_runtime.h>
#include <math.h>

// ---------------------------------------------------------------------------
// WindowAttention (Swin-V2 style) on GB300
//   x:(512,144,512) -> out:(512,144,512) fp32
//   H=16 heads, hd=32, WIN=12, N=144, NW=64 windows
// ---------------------------------------------------------------------------

#define BW   512          // number of windows*batch
#define NTOK 144          // tokens per window
#define DIM  512
#define NH   16
#define HD   32
#define NWIN 64
#define KDIM 512

// scratch (device globals: allocation-free rule). Referenced ONLY from device
// code — passing these as kernel args from host passes the host shadow
// address (that was the round-2/3 bug).
__device__ float g_q[(size_t)BW * NH * NTOK * HD];
__device__ float g_k[(size_t)BW * NH * NTOK * HD];
__device__ float g_v[(size_t)BW * NH * NTOK * HD];
__device__ float g_o[(size_t)BW * NTOK * DIM];
__device__ float g_cpb[NH * 529];   // 16*sigmoid(rpb) per head, (2W-1)^2=529

// ---------------------------------------------------------------------------
// CPB MLP: table[529][16] = relu(coords @ w1.T + b1) @ w2.T; store 16*sigmoid
// ---------------------------------------------------------------------------
__global__ void cpb_kernel(const float* __restrict__ w1,
                           const float* __restrict__ b1,
                           const float* __restrict__ w2)
{
    int idx = blockIdx.x * 128 + threadIdx.x;
    if (idx >= 529) return;
    int a = idx / 23, bb = idx % 23;
    float ra = (float)(a - 11);
    float rb = (float)(bb - 11);
    // f(r) = sign(t)*log2(|t|+1)/log2(8),  t = r/11*8
    float ta = ra * (8.0f / 11.0f);
    float tb = rb * (8.0f / 11.0f);
    float t0 = copysignf(log2f(fabsf(ta) + 1.0f) * (1.0f / 3.0f), ta);
    float t1 = copysignf(log2f(fabsf(tb) + 1.0f) * (1.0f / 3.0f), tb);

    float acc[NH];
#pragma unroll
    for (int h = 0; h < NH; h++) acc[h] = 0.0f;

    for (int k = 0; k < 512; k++) {
        float hid = fmaf(t0, w1[2 * k], fmaf(t1, w1[2 * k + 1], b1[k]));
        hid = fmaxf(hid, 0.0f);
#pragma unroll
        for (int h = 0; h < NH; h++) acc[h] = fmaf(hid, w2[h * 512 + k], acc[h]);
    }
#pragma unroll
    for (int h = 0; h < NH; h++)
        g_cpb[h * 529 + idx] = 16.0f / (1.0f + __expf(-acc[h]));
}

// ---------------------------------------------------------------------------
// SGEMM: C[M][Ncols] = A[M][512] @ W[Ncols][512]^T (+bias / scatter epilogue)
// 128x128 tile, BK=16, 256 threads, 8x8 microtile.
// MODE 0: QKV — A = x (kernel arg), scatter into g_q/g_k/g_v with q/v bias
// MODE 1: proj — A = g_o (device symbol, resolved IN DEVICE CODE),
//                C[r][c] = acc + biasA[c]
// ---------------------------------------------------------------------------
template <int MODE>
__global__ __launch_bounds__(256, 2)
void gemm_k(const float* __restrict__ Ain, const float* __restrict__ W,
            const float* __restrict__ biasA, const float* __restrict__ biasB,
            float* __restrict__ C)
{
    // device-side symbol resolution (host cannot pass g_o's device address)
    const float* __restrict__ A = (MODE == 1) ? (const float*)g_o : Ain;

    __shared__ float As[16][128];
    __shared__ float Bs[16][128];

    int tid = threadIdx.x;
    int m0 = blockIdx.y * 128;
    int n0 = blockIdx.x * 128;
    int ty = tid >> 4;         // 0..15
    int tx = tid & 15;         // 0..15

    int lrow = tid >> 2;       // 0..63
    int lk4  = (tid & 3) * 4;  // 0,4,8,12

    float acc[8][8];
#pragma unroll
    for (int i = 0; i < 8; i++)
#pragma unroll
        for (int j = 0; j < 8; j++) acc[i][j] = 0.0f;

    for (int k0 = 0; k0 < KDIM; k0 += 16) {
        float4 a0 = *(const float4*)&A[(size_t)(m0 + lrow) * KDIM + k0 + lk4];
        float4 a1 = *(const float4*)&A[(size_t)(m0 + lrow + 64) * KDIM + k0 + lk4];
        float4 b0 = *(const float4*)&W[(size_t)(n0 + lrow) * KDIM + k0 + lk4];
        float4 b1 = *(const float4*)&W[(size_t)(n0 + lrow + 64) * KDIM + k0 + lk4];
        __syncthreads();
        As[lk4 + 0][lrow] = a0.x; As[lk4 + 1][lrow] = a0.y;
        As[lk4 + 2][lrow] = a0.z; As[lk4 + 3][lrow] = a0.w;
        As[lk4 + 0][lrow + 64] = a1.x; As[lk4 + 1][lrow + 64] = a1.y;
        As[lk4 + 2][lrow + 64] = a1.z; As[lk4 + 3][lrow + 64] = a1.w;
        Bs[lk4 + 0][lrow] = b0.x; Bs[lk4 + 1][lrow] = b0.y;
        Bs[lk4 + 2][lrow] = b0.z; Bs[lk4 + 3][lrow] = b0.w;
        Bs[lk4 + 0][lrow + 64] = b1.x; Bs[lk4 + 1][lrow + 64] = b1.y;
        Bs[lk4 + 2][lrow + 64] = b1.z; Bs[lk4 + 3][lrow + 64] = b1.w;
        __syncthreads();

#pragma unroll
        for (int kk = 0; kk < 16; kk++) {
            float av[8], bv[8];
            *(float4*)&av[0] = *(const float4*)&As[kk][ty * 8];
            *(float4*)&av[4] = *(const float4*)&As[kk][ty * 8 + 4];
            *(float4*)&bv[0] = *(const float4*)&Bs[kk][tx * 8];
            *(float4*)&bv[4] = *(const float4*)&Bs[kk][tx * 8 + 4];
#pragma unroll
            for (int i = 0; i < 8; i++)
#pragma unroll
                for (int j = 0; j < 8; j++)
                    acc[i][j] = fmaf(av[i], bv[j], acc[i][j]);
        }
    }

    if (MODE == 0) {
#pragma unroll
        for (int i = 0; i < 8; i++) {
            int r = m0 + ty * 8 + i;
            int bwin = r / NTOK;
            int n = r - bwin * NTOK;
#pragma unroll
            for (int j = 0; j < 8; j++) {
                int c = n0 + tx * 8 + j;
                int which = c >> 9;      // 0=q 1=k 2=v
                int cc = c & 511;
                int hh = cc >> 5;
                int dd = cc & 31;
                float bias = (which == 0) ? biasA[cc] : (which == 2 ? biasB[cc] : 0.0f);
                float v = acc[i][j] + bias;
                float* dst = (which == 0) ? g_q : (which == 1 ? g_k : g_v);
                dst[((((size_t)bwin * NH + hh) * NTOK) + n) * HD + dd] = v;
            }
        }
    } else {
#pragma unroll
        for (int i = 0; i < 8; i++) {
            size_t r = m0 + ty * 8 + i;
#pragma unroll
            for (int j = 0; j < 8; j++) {
                int c = n0 + tx * 8 + j;
                C[r * DIM + c] = acc[i][j] + biasA[c];
            }
        }
    }
}

// ---------------------------------------------------------------------------
// Attention: one block per (b,h). 256 threads = 8 warps, 2 rows per warp iter.
// STATIC shared <= 48KB (no cudaFuncSetAttribute needed):
//   kn, vv: 144*32 floats each, XOR-swizzled (addr = row*32 + (d ^ (row&31)))
//   bs: 529 CPB bias entries; ps: 16*144 softmax probs (2 rows per warp)
// Total = 36864 + 2116 + 9216 = 48196 bytes < 49152.
// ---------------------------------------------------------------------------
__global__ __launch_bounds__(256)
void attn_kernel(const float* __restrict__ mask,
                 const float* __restrict__ logit_scale)
{
    __shared__ float kn[NTOK * 32];
    __shared__ float vv[NTOK * 32];
    __shared__ float bs[529];
    __shared__ float ps[16 * NTOK];

    int bid = blockIdx.x;
    int b = bid >> 4;
    int h = bid & 15;
    int tid = threadIdx.x;
    int w = tid >> 5;
    int lane = tid & 31;

    // CPB bias for this head
    for (int t = tid; t < 529; t += 256) bs[t] = g_cpb[h * 529 + t];

    // load k/v tiles, swizzled
    size_t base = (size_t)bid * (NTOK * HD);
    for (int t = tid; t < NTOK * 32; t += 256) {
        int row = t >> 5;
        int d = t & 31;
        int sw = row * 32 + (d ^ (row & 31));
        kn[sw] = g_k[base + t];
        vv[sw] = g_v[base + t];
    }
    __syncthreads();

    // l2-normalize k rows (one thread per row)
    if (tid < NTOK) {
        int sx = tid & 31;
        float ss = 0.0f;
#pragma unroll
        for (int d = 0; d < HD; d++) {
            float kv = kn[tid * 32 + (d ^ sx)];
            ss = fmaf(kv, kv, ss);
        }
        float inv = 1.0f / fmaxf(sqrtf(ss), 1e-12f);
#pragma unroll
        for (int d = 0; d < HD; d++)
            kn[tid * 32 + (d ^ sx)] *= inv;
    }
    __syncthreads();

    float scale = __expf(fminf(logit_scale[h], 4.605170185988092f)); // ln(100)
    const float* mbase = mask + (size_t)(b & (NWIN - 1)) * (NTOK * NTOK);

    // 72 row-pairs, distributed over 8 warps
    for (int ii = w; ii < 72; ii += 8) {
        int i0 = 2 * ii, i1 = i0 + 1;
        int yi0 = i0 / 12, xi0 = i0 - yi0 * 12;
        int yi1 = i1 / 12, xi1 = i1 - yi1 * 12;

        // load + normalize this iteration's two q rows (lane = d index)
        float q0 = g_q[base + (size_t)i0 * HD + lane];
        float q1 = g_q[base + (size_t)i1 * HD + lane];
        float ss0 = q0 * q0, ss1 = q1 * q1;
#pragma unroll
        for (int off = 16; off; off >>= 1) {
            ss0 += __shfl_xor_sync(0xffffffffu, ss0, off);
            ss1 += __shfl_xor_sync(0xffffffffu, ss1, off);
        }
        q0 *= scale / fmaxf(sqrtf(ss0), 1e-12f);
        q1 *= scale / fmaxf(sqrtf(ss1), 1e-12f);

        float s0[5], s1[5];
#pragma unroll
        for (int t = 0; t < 5; t++) { s0[t] = 0.0f; s1[t] = 0.0f; }

#pragma unroll
        for (int d = 0; d < HD; d++) {
            float qa = __shfl_sync(0xffffffffu, q0, d);
            float qb = __shfl_sync(0xffffffffu, q1, d);
#pragma unroll
            for (int t = 0; t < 5; t++) {
                int j = lane + 32 * t;
                int jc = (j < NTOK) ? j : (NTOK - 1);
                float kv = kn[jc * 32 + (d ^ (jc & 31))];
                s0[t] = fmaf(qa, kv, s0[t]);
                s1[t] = fmaf(qb, kv, s1[t]);
            }
        }

        float m0 = -1e30f, m1 = -1e30f;
#pragma unroll
        for (int t = 0; t < 5; t++) {
            int j = lane + 32 * t;
            if (j < NTOK) {
                int yj = j / 12, xj = j - yj * 12;
                float b0v = bs[(yi0 - yj + 11) * 23 + (xi0 - xj + 11)];
                float b1v = bs[(yi1 - yj + 11) * 23 + (xi1 - xj + 11)];
                s0[t] += b0v + mbase[i0 * NTOK + j];
                s1[t] += b1v + mbase[i1 * NTOK + j];
                m0 = fmaxf(m0, s0[t]);
                m1 = fmaxf(m1, s1[t]);
            } else {
                s0[t] = -1e30f;
                s1[t] = -1e30f;
            }
        }
#pragma unroll
        for (int off = 16; off; off >>= 1) {
            m0 = fmaxf(m0, __shfl_xor_sync(0xffffffffu, m0, off));
            m1 = fmaxf(m1, __shfl_xor_sync(0xffffffffu, m1, off));
        }
        float sum0 = 0.0f, sum1 = 0.0f;
#pragma unroll
        for (int t = 0; t < 5; t++) {
            int j = lane + 32 * t;
            if (j < NTOK) {
                float p0 = __expf(s0[t] - m0);
                float p1 = __expf(s1[t] - m1);
                s0[t] = p0; s1[t] = p1;
                sum0 += p0; sum1 += p1;
            }
        }
#pragma unroll
        for (int off = 16; off; off >>= 1) {
            sum0 += __shfl_xor_sync(0xffffffffu, sum0, off);
            sum1 += __shfl_xor_sync(0xffffffffu, sum1, off);
        }
        float r0 = 1.0f / sum0;
        float r1 = 1.0f / sum1;
        float* p0p = ps + (2 * w) * NTOK;
        float* p1p = p0p + NTOK;
#pragma unroll
        for (int t = 0; t < 5; t++) {
            int j = lane + 32 * t;
            if (j < NTOK) {
                p0p[j] = s0[t] * r0;
                p1p[j] = s1[t] * r1;
            }
        }
        __syncwarp();

        float o0 = 0.0f, o1 = 0.0f;
#pragma unroll 8
        for (int j = 0; j < NTOK; j++) {
            float vval = vv[j * 32 + (lane ^ (j & 31))];
            o0 = fmaf(p0p[j], vval, o0);
            o1 = fmaf(p1p[j], vval, o1);
        }
        size_t obase = ((size_t)b * NTOK) * DIM + h * HD + lane;
        g_o[obase + (size_t)i0 * DIM] = o0;
        g_o[obase + (size_t)i1 * DIM] = o1;
        __syncwarp();
    }
}

// ---------------------------------------------------------------------------
// launch — inputs resolved by element count (robust to metadata ordering).
// Only harness-provided pointers are passed as kernel args; device scratch
// symbols are referenced inside device code exclusively.
// ---------------------------------------------------------------------------
extern "C" void kernel_launch(void* const* d_in, const int* in_sizes, int n_in,
                              void* d_out, int out_size)
{
    int ix = 0, imask = 1, iwqkv = 2, ils = 5, iw1 = 6, iw2 = 8, iwproj = 9;
    int small[4] = {3, 4, 7, 10};
    int ns = 0;
    int sm_tmp[8];
    int fx = -1, fmask = -1, fwqkv = -1, fls = -1, fw1 = -1, fw2 = -1, fwp = -1;
    for (int i = 0; i < n_in; i++) {
        switch (in_sizes[i]) {
            case 37748736: fx = i; break;       // x
            case 1327104:  fmask = i; break;    // mask
            case 786432:   fwqkv = i; break;    // w_qkv
            case 16:       fls = i; break;      // logit_scale
            case 1024:     fw1 = i; break;      // w1
            case 8192:     fw2 = i; break;      // w2
            case 262144:   fwp = i; break;      // w_proj
            case 512:      if (ns < 8) sm_tmp[ns++] = i; break;
            default: break;
        }
    }
    if (fx >= 0 && fmask >= 0 && fwqkv >= 0 && fls >= 0 && fw1 >= 0 &&
        fw2 >= 0 && fwp >= 0 && ns >= 4) {
        ix = fx; imask = fmask; iwqkv = fwqkv; ils = fls;
        iw1 = fw1; iw2 = fw2; iwproj = fwp;
        for (int t = 0; t < 4; t++) small[t] = sm_tmp[t];
    }

    const float* x           = (const float*)d_in[ix];
    const float* mask        = (const float*)d_in[imask];
    const float* w_qkv       = (const float*)d_in[iwqkv];
    const float* q_bias      = (const float*)d_in[small[0]];
    const float* v_bias      = (const float*)d_in[small[1]];
    const float* logit_scale = (const float*)d_in[ils];
    const float* w1          = (const float*)d_in[iw1];
    const float* b1          = (const float*)d_in[small[2]];
    const float* w2          = (const float*)d_in[iw2];
    const float* w_proj      = (const float*)d_in[iwproj];
    const float* b_proj      = (const float*)d_in[small[3]];
    float* out = (float*)d_out;
    (void)out_size;

    // 1) CPB bias table (529 entries x 16 heads)
    cpb_kernel<<<5, 128>>>(w1, b1, w2);

    // 2) QKV GEMM: (73728 x 512) @ (1536 x 512)^T, scatter epilogue
    {
        dim3 grid(1536 / 128, (BW * NTOK) / 128);
        gemm_k<0><<<grid, 256>>>(x, w_qkv, q_bias, v_bias, nullptr);
    }

    // 3) attention per (b,h) — static smem only
    attn_kernel<<<BW * NH, 256>>>(mask, logit_scale);

    // 4) output projection: (73728 x 512) @ (512 x 512)^T + b_proj
    //    A = g_o resolved inside the kernel (MODE 1); arg is ignored.
    {
        dim3 grid(DIM / 128, (BW * NTOK) / 128);
        gemm_k<1><<<grid, 256>>>(nullptr, w_proj, b_proj, nullptr, out);
    }
}

// round 6
// speedup vs baseline: 1.6257x; 1.6257x over previous
#include <cuda_runtime.h>
#include <cuda_bf16.h>
#include <math.h>
#include <stdint.h>

// ---------------------------------------------------------------------------
// WindowAttention (Swin-V2 style) on GB300 — mma.sync bf16-split GEMMs
//   (tcgen05 unavailable: harness compiles PTX at compute_103, no 'a' feats)
//   x:(512,144,512) -> out:(512,144,512) fp32
// ---------------------------------------------------------------------------

#define BW   512
#define NTOK 144
#define DIM  512
#define NH   16
#define HD   32
#define NWIN 64
#define KDIM 512

// device scratch — referenced ONLY from device code (host shadow-ptr trap)
__device__ float g_q[(size_t)BW * NH * NTOK * HD];
__device__ float g_k[(size_t)BW * NH * NTOK * HD];
__device__ float g_v[(size_t)BW * NH * NTOK * HD];
__device__ float g_o[(size_t)BW * NTOK * DIM];
__device__ float g_cpb[NH * 529];

static __device__ __forceinline__ uint32_t smem_u32(const void* p) {
    uint32_t a;
    asm("{ .reg .u64 t; cvta.to.shared.u64 t, %1; cvt.u32.u64 %0, t; }"
        : "=r"(a) : "l"(p));
    return a;
}

#define LDM4(r, addr) \
    asm volatile("ldmatrix.sync.aligned.m8n8.x4.shared.b16 {%0,%1,%2,%3}, [%4];" \
                 : "=r"((r)[0]), "=r"((r)[1]), "=r"((r)[2]), "=r"((r)[3]) \
                 : "r"(addr))

#define MMA16816(d, a, b0, b1) \
    asm volatile("mma.sync.aligned.m16n8k16.row.col.f32.bf16.bf16.f32 " \
                 "{%0,%1,%2,%3}, {%4,%5,%6,%7}, {%8,%9}, {%0,%1,%2,%3};" \
                 : "+f"((d)[0]), "+f"((d)[1]), "+f"((d)[2]), "+f"((d)[3]) \
                 : "r"((a)[0]), "r"((a)[1]), "r"((a)[2]), "r"((a)[3]), \
                   "r"(b0), "r"(b1))

__device__ __forceinline__ uint32_t pk_bf2(__nv_bfloat16 a, __nv_bfloat16 b) {
    return (uint32_t)__bfloat16_as_ushort(a) |
           ((uint32_t)__bfloat16_as_ushort(b) << 16);
}

// split float4 into bf16 hi (rounded) + lo (residual), packed as uint2 each
__device__ __forceinline__ void split4(float4 v, uint2& hi, uint2& lo) {
    __nv_bfloat16 h0 = __float2bfloat16(v.x);
    __nv_bfloat16 h1 = __float2bfloat16(v.y);
    __nv_bfloat16 h2 = __float2bfloat16(v.z);
    __nv_bfloat16 h3 = __float2bfloat16(v.w);
    __nv_bfloat16 l0 = __float2bfloat16(v.x - __bfloat162float(h0));
    __nv_bfloat16 l1 = __float2bfloat16(v.y - __bfloat162float(h1));
    __nv_bfloat16 l2 = __float2bfloat16(v.z - __bfloat162float(h2));
    __nv_bfloat16 l3 = __float2bfloat16(v.w - __bfloat162float(h3));
    hi = make_uint2(pk_bf2(h0, h1), pk_bf2(h2, h3));
    lo = make_uint2(pk_bf2(l0, l1), pk_bf2(l2, l3));
}

// ---------------------------------------------------------------------------
// CPB MLP
// ---------------------------------------------------------------------------
__global__ void cpb_kernel(const float* __restrict__ w1,
                           const float* __restrict__ b1,
                           const float* __restrict__ w2)
{
    int idx = blockIdx.x * 128 + threadIdx.x;
    if (idx >= 529) return;
    int a = idx / 23, bb = idx % 23;
    float ta = (float)(a - 11) * (8.0f / 11.0f);
    float tb = (float)(bb - 11) * (8.0f / 11.0f);
    float t0 = copysignf(log2f(fabsf(ta) + 1.0f) * (1.0f / 3.0f), ta);
    float t1 = copysignf(log2f(fabsf(tb) + 1.0f) * (1.0f / 3.0f), tb);

    float acc[NH];
#pragma unroll
    for (int h = 0; h < NH; h++) acc[h] = 0.0f;
    for (int k = 0; k < 512; k++) {
        float hid = fmaf(t0, w1[2 * k], fmaf(t1, w1[2 * k + 1], b1[k]));
        hid = fmaxf(hid, 0.0f);
#pragma unroll
        for (int h = 0; h < NH; h++) acc[h] = fmaf(hid, w2[h * 512 + k], acc[h]);
    }
#pragma unroll
    for (int h = 0; h < NH; h++)
        g_cpb[h * 529 + idx] = 16.0f / (1.0f + __expf(-acc[h]));
}

// ---------------------------------------------------------------------------
// mma.sync GEMM: C[M][Nc] = A[M][512] @ W[Nc][512]^T, bf16-split 3-pass
// CTA 128x128, BK=16 per chunk, 32 chunks, double-buffered static smem.
// smem tiles stored as contiguous 8x8-b16 (128B) blocks in ldmatrix.x4 order.
// Warp grid 2(M)x4(N): warp tile 64x32 = 4x4 m16n8 frags.
// MODE 0: A = x (arg); scatter epilogue to g_q/g_k/g_v with q/v bias.
// MODE 1: A = g_o (device symbol); C[r][c] = acc + biasA[c].
// ---------------------------------------------------------------------------
#define CHUNKS 32      // 512 / 16
#define STG 16384      // Ahi(4K) Alo(4K) Bhi(4K) Blo(4K)

template <int MODE>
__global__ __launch_bounds__(256)
void gemm_m(const float* __restrict__ Ain, const float* __restrict__ W,
            const float* __restrict__ biasA, const float* __restrict__ biasB,
            float* __restrict__ C)
{
    const float* __restrict__ A = (MODE == 1) ? (const float*)g_o : Ain;

    __shared__ __align__(16) unsigned char sb[2][STG];

    const int tid = threadIdx.x;
    const int lane = tid & 31;
    const int w = tid >> 5;
    const int wm = w & 1;        // M half (0/1)
    const int wn = w >> 1;       // N quarter (0..3)
    const int m0 = blockIdx.y * 128;
    const int n0 = blockIdx.x * 128;

    float acc[4][4][4];
#pragma unroll
    for (int i = 0; i < 4; i++)
#pragma unroll
        for (int j = 0; j < 4; j++)
#pragma unroll
            for (int r = 0; r < 4; r++) acc[i][j][r] = 0.0f;

    // loader: thread handles float4 ids f = tid, tid+256  (512 per matrix)
    int rowi[2], k4i[2], aoff[2], boff[2];
#pragma unroll
    for (int i = 0; i < 2; i++) {
        int f = tid + 256 * i;
        int row = f >> 2;            // 0..127
        int k4 = (f & 3) * 4;        // 0,4,8,12
        rowi[i] = row; k4i[i] = k4;
        int ablk = ((k4 >> 3) & 1) * 2 + ((row >> 3) & 1);
        aoff[i] = ((row >> 4) * 4 + ablk) * 128 + (row & 7) * 16 + (k4 & 7) * 2;
        int bblk = ((row >> 3) & 1) * 2 + ((k4 >> 3) & 1);
        boff[i] = ((row >> 4) * 4 + bblk) * 128 + (row & 7) * 16 + (k4 & 7) * 2;
    }

    float4 pa[2], pb[2];
    auto load_gmem = [&](int c) {
#pragma unroll
        for (int i = 0; i < 2; i++) {
            pa[i] = *(const float4*)&A[(size_t)(m0 + rowi[i]) * KDIM + c * 16 + k4i[i]];
            pb[i] = *(const float4*)&W[(size_t)(n0 + rowi[i]) * KDIM + c * 16 + k4i[i]];
        }
    };
    auto store_stage = [&](int st) {
        unsigned char* base = sb[st];
#pragma unroll
        for (int i = 0; i < 2; i++) {
            uint2 hi, lo;
            split4(pa[i], hi, lo);
            *(uint2*)(base + aoff[i]) = hi;
            *(uint2*)(base + 4096 + aoff[i]) = lo;
            split4(pb[i], hi, lo);
            *(uint2*)(base + 8192 + boff[i]) = hi;
            *(uint2*)(base + 12288 + boff[i]) = lo;
        }
    };

    const uint32_t lmoff = (uint32_t)((lane >> 3) * 128 + (lane & 7) * 16);

    auto compute_stage = [&](int st) {
        uint32_t sbase = smem_u32(sb[st]);
        uint32_t a_lm = sbase + (uint32_t)(wm * 4) * 512u + lmoff;
        uint32_t b_lm = sbase + 8192u + (uint32_t)(wn * 2) * 512u + lmoff;

        uint32_t ahi[4][4], alo[4][4], bhi[2][4], blo[2][4];
#pragma unroll
        for (int ti = 0; ti < 4; ti++) LDM4(ahi[ti], a_lm + ti * 512);
#pragma unroll
        for (int g = 0; g < 2; g++) LDM4(bhi[g], b_lm + g * 512);
#pragma unroll
        for (int ti = 0; ti < 4; ti++)
#pragma unroll
            for (int tj = 0; tj < 4; tj++)
                MMA16816(acc[ti][tj], ahi[ti],
                         bhi[tj >> 1][(tj & 1) * 2], bhi[tj >> 1][(tj & 1) * 2 + 1]);
#pragma unroll
        for (int g = 0; g < 2; g++) LDM4(blo[g], b_lm + 4096 + g * 512);
#pragma unroll
        for (int ti = 0; ti < 4; ti++)
#pragma unroll
            for (int tj = 0; tj < 4; tj++)
                MMA16816(acc[ti][tj], ahi[ti],
                         blo[tj >> 1][(tj & 1) * 2], blo[tj >> 1][(tj & 1) * 2 + 1]);
#pragma unroll
        for (int ti = 0; ti < 4; ti++) LDM4(alo[ti], a_lm + 4096 + ti * 512);
#pragma unroll
        for (int ti = 0; ti < 4; ti++)
#pragma unroll
            for (int tj = 0; tj < 4; tj++)
                MMA16816(acc[ti][tj], alo[ti],
                         bhi[tj >> 1][(tj & 1) * 2], bhi[tj >> 1][(tj & 1) * 2 + 1]);
    };

    // prologue
    load_gmem(0);
    store_stage(0);
    __syncthreads();

#pragma unroll 2
    for (int c = 0; c < CHUNKS; c++) {
        if (c + 1 < CHUNKS) load_gmem(c + 1);
        compute_stage(c & 1);
        if (c + 1 < CHUNKS) store_stage((c + 1) & 1);
        __syncthreads();
    }

    // epilogue: frag (ti,tj): c0,c1=(r, n),(r, n+1); c2,c3=(r+8, n),(r+8, n+1)
#pragma unroll
    for (int ti = 0; ti < 4; ti++) {
#pragma unroll
        for (int half = 0; half < 2; half++) {
            int m = m0 + wm * 64 + ti * 16 + (lane >> 2) + half * 8;
            int bwin = 0, nt = 0;
            if (MODE == 0) { bwin = m / NTOK; nt = m - bwin * NTOK; }
#pragma unroll
            for (int tj = 0; tj < 4; tj++) {
                int n = n0 + wn * 32 + tj * 8 + (lane & 3) * 2;
                float v0 = acc[ti][tj][half * 2 + 0];
                float v1 = acc[ti][tj][half * 2 + 1];
                if (MODE == 0) {
                    int which = n >> 9;          // 0=q 1=k 2=v
                    int cc = n & 511;
                    int hh = cc >> 5;
                    int dd = cc & 31;
                    float b0 = (which == 0) ? biasA[cc]
                             : (which == 2 ? biasB[cc] : 0.0f);
                    float b1 = (which == 0) ? biasA[cc + 1]
                             : (which == 2 ? biasB[cc + 1] : 0.0f);
                    float* dst = (which == 0) ? g_q : (which == 1 ? g_k : g_v);
                    *(float2*)&dst[((((size_t)bwin * NH + hh) * NTOK) + nt) * HD + dd] =
                        make_float2(v0 + b0, v1 + b1);
                } else {
                    *(float2*)&C[(size_t)m * DIM + n] =
                        make_float2(v0 + biasA[n], v1 + biasA[n + 1]);
                }
            }
        }
    }
}

// ---------------------------------------------------------------------------
// Attention (unchanged from R4-pass): one block per (b,h), static smem 48196B
// ---------------------------------------------------------------------------
__global__ __launch_bounds__(256)
void attn_kernel(const float* __restrict__ mask,
                 const float* __restrict__ logit_scale)
{
    __shared__ float kn[NTOK * 32];
    __shared__ float vv[NTOK * 32];
    __shared__ float bs[529];
    __shared__ float ps[16 * NTOK];

    int bid = blockIdx.x;
    int b = bid >> 4;
    int h = bid & 15;
    int tid = threadIdx.x;
    int w = tid >> 5;
    int lane = tid & 31;

    for (int t = tid; t < 529; t += 256) bs[t] = g_cpb[h * 529 + t];

    size_t base = (size_t)bid * (NTOK * HD);
    for (int t = tid; t < NTOK * 32; t += 256) {
        int row = t >> 5;
        int d = t & 31;
        int sw = row * 32 + (d ^ (row & 31));
        kn[sw] = g_k[base + t];
        vv[sw] = g_v[base + t];
    }
    __syncthreads();

    if (tid < NTOK) {
        int sx = tid & 31;
        float ss = 0.0f;
#pragma unroll
        for (int d = 0; d < HD; d++) {
            float kv = kn[tid * 32 + (d ^ sx)];
            ss = fmaf(kv, kv, ss);
        }
        float inv = 1.0f / fmaxf(sqrtf(ss), 1e-12f);
#pragma unroll
        for (int d = 0; d < HD; d++)
            kn[tid * 32 + (d ^ sx)] *= inv;
    }
    __syncthreads();

    float scale = __expf(fminf(logit_scale[h], 4.605170185988092f));
    const float* mbase = mask + (size_t)(b & (NWIN - 1)) * (NTOK * NTOK);

    for (int ii = w; ii < 72; ii += 8) {
        int i0 = 2 * ii, i1 = i0 + 1;
        int yi0 = i0 / 12, xi0 = i0 - yi0 * 12;
        int yi1 = i1 / 12, xi1 = i1 - yi1 * 12;

        float q0 = g_q[base + (size_t)i0 * HD + lane];
        float q1 = g_q[base + (size_t)i1 * HD + lane];
        float ss0 = q0 * q0, ss1 = q1 * q1;
#pragma unroll
        for (int off = 16; off; off >>= 1) {
            ss0 += __shfl_xor_sync(0xffffffffu, ss0, off);
            ss1 += __shfl_xor_sync(0xffffffffu, ss1, off);
        }
        q0 *= scale / fmaxf(sqrtf(ss0), 1e-12f);
        q1 *= scale / fmaxf(sqrtf(ss1), 1e-12f);

        float s0[5], s1[5];
#pragma unroll
        for (int t = 0; t < 5; t++) { s0[t] = 0.0f; s1[t] = 0.0f; }

#pragma unroll
        for (int d = 0; d < HD; d++) {
            float qa = __shfl_sync(0xffffffffu, q0, d);
            float qb = __shfl_sync(0xffffffffu, q1, d);
#pragma unroll
            for (int t = 0; t < 5; t++) {
                int j = lane + 32 * t;
                int jc = (j < NTOK) ? j : (NTOK - 1);
                float kv = kn[jc * 32 + (d ^ (jc & 31))];
                s0[t] = fmaf(qa, kv, s0[t]);
                s1[t] = fmaf(qb, kv, s1[t]);
            }
        }

        float m0 = -1e30f, m1 = -1e30f;
#pragma unroll
        for (int t = 0; t < 5; t++) {
            int j = lane + 32 * t;
            if (j < NTOK) {
                int yj = j / 12, xj = j - yj * 12;
                float b0v = bs[(yi0 - yj + 11) * 23 + (xi0 - xj + 11)];
                float b1v = bs[(yi1 - yj + 11) * 23 + (xi1 - xj + 11)];
                s0[t] += b0v + mbase[i0 * NTOK + j];
                s1[t] += b1v + mbase[i1 * NTOK + j];
                m0 = fmaxf(m0, s0[t]);
                m1 = fmaxf(m1, s1[t]);
            } else {
                s0[t] = -1e30f;
                s1[t] = -1e30f;
            }
        }
#pragma unroll
        for (int off = 16; off; off >>= 1) {
            m0 = fmaxf(m0, __shfl_xor_sync(0xffffffffu, m0, off));
            m1 = fmaxf(m1, __shfl_xor_sync(0xffffffffu, m1, off));
        }
        float sum0 = 0.0f, sum1 = 0.0f;
#pragma unroll
        for (int t = 0; t < 5; t++) {
            int j = lane + 32 * t;
            if (j < NTOK) {
                float p0 = __expf(s0[t] - m0);
                float p1 = __expf(s1[t] - m1);
                s0[t] = p0; s1[t] = p1;
                sum0 += p0; sum1 += p1;
            }
        }
#pragma unroll
        for (int off = 16; off; off >>= 1) {
            sum0 += __shfl_xor_sync(0xffffffffu, sum0, off);
            sum1 += __shfl_xor_sync(0xffffffffu, sum1, off);
        }
        float r0 = 1.0f / sum0;
        float r1 = 1.0f / sum1;
        float* p0p = ps + (2 * w) * NTOK;
        float* p1p = p0p + NTOK;
#pragma unroll
        for (int t = 0; t < 5; t++) {
            int j = lane + 32 * t;
            if (j < NTOK) {
                p0p[j] = s0[t] * r0;
                p1p[j] = s1[t] * r1;
            }
        }
        __syncwarp();

        float o0 = 0.0f, o1 = 0.0f;
#pragma unroll 8
        for (int j = 0; j < NTOK; j++) {
            float vval = vv[j * 32 + (lane ^ (j & 31))];
            o0 = fmaf(p0p[j], vval, o0);
            o1 = fmaf(p1p[j], vval, o1);
        }
        size_t obase = ((size_t)b * NTOK) * DIM + h * HD + lane;
        g_o[obase + (size_t)i0 * DIM] = o0;
        g_o[obase + (size_t)i1 * DIM] = o1;
        __syncwarp();
    }
}

// ---------------------------------------------------------------------------
// launch — size-based input resolution (order-robust)
// ---------------------------------------------------------------------------
extern "C" void kernel_launch(void* const* d_in, const int* in_sizes, int n_in,
                              void* d_out, int out_size)
{
    int ix = 0, imask = 1, iwqkv = 2, ils = 5, iw1 = 6, iw2 = 8, iwproj = 9;
    int small[4] = {3, 4, 7, 10};
    int ns = 0;
    int sm_tmp[8];
    int fx = -1, fmask = -1, fwqkv = -1, fls = -1, fw1 = -1, fw2 = -1, fwp = -1;
    for (int i = 0; i < n_in; i++) {
        switch (in_sizes[i]) {
            case 37748736: fx = i; break;
            case 1327104:  fmask = i; break;
            case 786432:   fwqkv = i; break;
            case 16:       fls = i; break;
            case 1024:     fw1 = i; break;
            case 8192:     fw2 = i; break;
            case 262144:   fwp = i; break;
            case 512:      if (ns < 8) sm_tmp[ns++] = i; break;
            default: break;
        }
    }
    if (fx >= 0 && fmask >= 0 && fwqkv >= 0 && fls >= 0 && fw1 >= 0 &&
        fw2 >= 0 && fwp >= 0 && ns >= 4) {
        ix = fx; imask = fmask; iwqkv = fwqkv; ils = fls;
        iw1 = fw1; iw2 = fw2; iwproj = fwp;
        for (int t = 0; t < 4; t++) small[t] = sm_tmp[t];
    }

    const float* x           = (const float*)d_in[ix];
    const float* mask        = (const float*)d_in[imask];
    const float* w_qkv       = (const float*)d_in[iwqkv];
    const float* q_bias      = (const float*)d_in[small[0]];
    const float* v_bias      = (const float*)d_in[small[1]];
    const float* logit_scale = (const float*)d_in[ils];
    const float* w1          = (const float*)d_in[iw1];
    const float* b1          = (const float*)d_in[small[2]];
    const float* w2          = (const float*)d_in[iw2];
    const float* w_proj      = (const float*)d_in[iwproj];
    const float* b_proj      = (const float*)d_in[small[3]];
    float* out = (float*)d_out;
    (void)out_size;

    // 1) CPB bias table
    cpb_kernel<<<5, 128>>>(w1, b1, w2);

    // 2) QKV: (73728 x 512) @ (1536 x 512)^T — mma.sync bf16-split
    {
        dim3 grid(1536 / 128, (BW * NTOK) / 128);
        gemm_m<0><<<grid, 256>>>(x, w_qkv, q_bias, v_bias, nullptr);
    }

    // 3) attention per (b,h)
    attn_kernel<<<BW * NH, 256>>>(mask, logit_scale);

    // 4) proj: (73728 x 512) @ (512 x 512)^T — mma.sync bf16-split
    {
        dim3 grid(DIM / 128, (BW * NTOK) / 128);
        gemm_m<1><<<grid, 256>>>(nullptr, w_proj, b_proj, nullptr, out);
    }
}